// round 7
// baseline (speedup 1.0000x reference)
#include <cuda_runtime.h>
#include <cuda_bf16.h>
#include <cstdint>

#define N_VOX 262144
#define HCH   64
#define KOFF  27
#define TILE_M 128
#define NT     128

#define WROW     72                    // padded W^T row: 72 bf16 = 144 B
#define WTILE_EL (HCH * WROW)          // 4608 elems per split tile
#define WTILE_B  (WTILE_EL * 2)        // 9216 B
#define WOFF_B   (2 * WTILE_B)         // 18432 B per offset (hi + lo)

// ---------------- device globals (no allocs allowed) ----------------
// Packed hi/lo bf16 features: pk[row*32 + j] = {bf16x2 hi(2j,2j+1), bf16x2 lo}
// Row N_VOX is the zero sentinel row.
__device__ __align__(16) uint2 g_pkx[(size_t)(N_VOX + 1) * 32];
__device__ __align__(16) uint2 g_pkm[(size_t)(N_VOX + 1) * 32];
__device__ __align__(16) __nv_bfloat16 g_Wt[2][KOFF][2][WTILE_EL];

// ---------------- helpers ----------------
__device__ __forceinline__ uint32_t smem_u32(const void* p) {
    return (uint32_t)__cvta_generic_to_shared(p);
}
__device__ __forceinline__ void cp_async16(uint32_t dst, const void* src) {
    asm volatile("cp.async.ca.shared.global [%0], [%1], 16;" :: "r"(dst), "l"(src));
}
__device__ __forceinline__ void cp_commit() { asm volatile("cp.async.commit_group;"); }
__device__ __forceinline__ void cp_wait0()  { asm volatile("cp.async.wait_group 0;"); }

__device__ __forceinline__ void ldmx4(uint32_t* r, uint32_t addr) {
    asm volatile("ldmatrix.sync.aligned.m8n8.x4.shared.b16 {%0,%1,%2,%3}, [%4];"
                 : "=r"(r[0]), "=r"(r[1]), "=r"(r[2]), "=r"(r[3]) : "r"(addr));
}
__device__ __forceinline__ void mma16816(float* c, const uint32_t* a,
                                         uint32_t b0, uint32_t b1) {
    asm volatile("mma.sync.aligned.m16n8k16.row.col.f32.bf16.bf16.f32 "
                 "{%0,%1,%2,%3}, {%4,%5,%6,%7}, {%8,%9}, {%0,%1,%2,%3};"
                 : "+f"(c[0]), "+f"(c[1]), "+f"(c[2]), "+f"(c[3])
                 : "r"(a[0]), "r"(a[1]), "r"(a[2]), "r"(a[3]), "r"(b0), "r"(b1));
}

// ---------------- W prep: W[k][kin][n] -> W^T[n][kin], hi/lo split, 144B rows
__global__ void prep_w(const float* __restrict__ Wa, const float* __restrict__ Wb) {
    int i = blockIdx.x * blockDim.x + threadIdx.x;
    const int total = KOFF * HCH * HCH;
    if (i >= 2 * total) return;
    const int w = i / total;
    const int r = i - w * total;           // k*4096 + kin*64 + n
    const float v = (w == 0) ? Wa[r] : Wb[r];
    const int k   = r >> 12;
    const int kin = (r >> 6) & 63;
    const int n   = r & 63;
    __nv_bfloat16 hi = __float2bfloat16(v);
    __nv_bfloat16 lo = __float2bfloat16(v - __bfloat162float(hi));
    g_Wt[w][k][0][n * WROW + kin] = hi;
    g_Wt[w][k][1][n * WROW + kin] = lo;
}

// ---------------- x prep: fp32 -> packed hi/lo bf16; also zero sentinel rows
__global__ void prep_x(const float* __restrict__ x) {
    const size_t i = (size_t)blockIdx.x * blockDim.x + threadIdx.x;
    const size_t total = (size_t)(N_VOX + 1) * 32;
    if (i >= total) return;
    uint2 o = make_uint2(0u, 0u);
    if (i < (size_t)N_VOX * 32) {
        const float2 v = ((const float2*)x)[i];
        __nv_bfloat162 h = __floats2bfloat162_rn(v.x, v.y);
        __nv_bfloat162 l = __floats2bfloat162_rn(v.x - __bfloat162float(h.x),
                                                 v.y - __bfloat162float(h.y));
        o.x = *(uint32_t*)&h;
        o.y = *(uint32_t*)&l;
        g_pkx[i] = o;
    } else {
        g_pkx[i] = o;
        g_pkm[i] = o;      // zero sentinel row of mid as well
    }
}

// ---------------- main conv kernel (HMMA mma.sync, packed A) ----------------
__global__ void __launch_bounds__(NT, 3)
spconv_mma(const uint2* __restrict__ pk,               // packed hi/lo feats
           const __nv_bfloat16* __restrict__ wt,       // [KOFF][2][WTILE_EL]
           const int* __restrict__ nbr,
           const float* __restrict__ resid,            // conv_b only
           float* __restrict__ outf,                   // conv_b only
           uint2* __restrict__ outpk,                  // conv_a only (relu+pack)
           int do_relu)
{
    __shared__ __align__(16) char wbuf[2][WOFF_B];

    const int t    = threadIdx.x;
    const int w    = t >> 5;
    const int lane = t & 31;
    const int row0 = blockIdx.x * TILE_M;
    const int gr   = row0 + 32 * w + (lane >> 2);   // fragment base row

    const uint32_t sb[2] = { smem_u32(wbuf[0]), smem_u32(wbuf[1]) };
    const int q = lane >> 3, e = lane & 7;
    const uint32_t lm_lane = (uint32_t)(((q & 1) * 8 + e) * 144 + (q >> 1) * 16);
    const int jlane = lane & 3;                     // pair-column within fragment

    float acc[2][8][4];
#pragma unroll
    for (int a = 0; a < 2; ++a)
#pragma unroll
        for (int j = 0; j < 8; ++j)
#pragma unroll
            for (int c = 0; c < 4; ++c) acc[a][j][c] = 0.0f;

    int idxc[4], idxn[4];
#define LOAD_IDX(dst, kk) do { \
        dst[0] = __ldg(&nbr[(size_t)(gr)      * KOFF + (kk)]); \
        dst[1] = __ldg(&nbr[(size_t)(gr + 8)  * KOFF + (kk)]); \
        dst[2] = __ldg(&nbr[(size_t)(gr + 16) * KOFF + (kk)]); \
        dst[3] = __ldg(&nbr[(size_t)(gr + 24) * KOFF + (kk)]); } while (0)

    // Load A fragments (both splits) for one 16-wide k-chunk straight from pk.
#define LOAD_APK(Ah, Al, idx, kc) do { \
        const int j0 = (kc) * 8 + jlane; \
        _Pragma("unroll") \
        for (int tt = 0; tt < 2; ++tt) { \
            _Pragma("unroll") \
            for (int h = 0; h < 2; ++h) { \
                const size_t base = (size_t)idx[tt * 2 + h] * 32; \
                const uint2 g0 = __ldg(&pk[base + j0]); \
                const uint2 g1 = __ldg(&pk[base + j0 + 4]); \
                Ah[tt][h]     = g0.x;  Al[tt][h]     = g0.y; \
                Ah[tt][2 + h] = g1.x;  Al[tt][2 + h] = g1.y; \
            } \
        } } while (0)

    // ---- prologue: stage W[0], load idx for k=0
    {
        const char* src = (const char*)wt;
        for (int i = t; i < WOFF_B / 16; i += NT)
            cp_async16(sb[0] + i * 16, src + i * 16);
        cp_commit();
    }
    LOAD_IDX(idxc, 0);
    cp_wait0();
    __syncthreads();

#pragma unroll 1
    for (int k = 0; k < KOFF; ++k) {
        const int b = k & 1;
        if (k < KOFF - 1) {
            const char* src = (const char*)wt + (size_t)(k + 1) * WOFF_B;
            for (int i = t; i < WOFF_B / 16; i += NT)
                cp_async16(sb[b ^ 1] + i * 16, src + i * 16);
            cp_commit();
            LOAD_IDX(idxn, k + 1);
        }
        const uint32_t sbuf = sb[b];

#pragma unroll
        for (int kc = 0; kc < 4; ++kc) {
            // A fragments: direct packed loads, no conversion math
            uint32_t Ah[2][4], Al[2][4];
            LOAD_APK(Ah, Al, idxc, kc);

            // B fragments for this k-chunk
            uint32_t bh[16], bl[16];
#pragma unroll
            for (int u = 0; u < 4; ++u) {
                const uint32_t a0 = sbuf + (uint32_t)(u * 16 * 144 + kc * 32) + lm_lane;
                ldmx4(&bh[u * 4], a0);
                ldmx4(&bl[u * 4], a0 + WTILE_B);
            }

            // 48 MMAs: 2 m-tiles x 8 n-tiles x 3 hi/lo combos
#pragma unroll
            for (int tt = 0; tt < 2; ++tt) {
#pragma unroll
                for (int j = 0; j < 8; ++j) {
                    const int u4 = (j >> 1) * 4 + (j & 1);
                    mma16816(acc[tt][j], Ah[tt], bh[u4], bh[u4 + 2]);
                    mma16816(acc[tt][j], Ah[tt], bl[u4], bl[u4 + 2]);
                    mma16816(acc[tt][j], Al[tt], bh[u4], bh[u4 + 2]);
                }
            }
        }

        if (k < KOFF - 1) cp_wait0();
        __syncthreads();
        idxc[0] = idxn[0]; idxc[1] = idxn[1];
        idxc[2] = idxn[2]; idxc[3] = idxn[3];
    }

    // ---- epilogue ----
    if (outpk) {
        // conv_a: relu, split to hi/lo, packed store (feeds conv_b's gather)
#pragma unroll
        for (int tt = 0; tt < 2; ++tt) {
#pragma unroll
            for (int half = 0; half < 2; ++half) {
                const int row = gr + 16 * tt + 8 * half;
#pragma unroll
                for (int j = 0; j < 8; ++j) {
                    float v0 = fmaxf(acc[tt][j][half * 2 + 0], 0.f);
                    float v1 = fmaxf(acc[tt][j][half * 2 + 1], 0.f);
                    __nv_bfloat162 h = __floats2bfloat162_rn(v0, v1);
                    __nv_bfloat162 l = __floats2bfloat162_rn(v0 - __bfloat162float(h.x),
                                                             v1 - __bfloat162float(h.y));
                    outpk[(size_t)row * 32 + j * 4 + jlane] =
                        make_uint2(*(uint32_t*)&h, *(uint32_t*)&l);
                }
            }
        }
    } else {
        // conv_b: residual add, fp32 store
#pragma unroll
        for (int tt = 0; tt < 2; ++tt) {
#pragma unroll
            for (int half = 0; half < 2; ++half) {
                const int row = gr + 16 * tt + 8 * half;
#pragma unroll
                for (int j = 0; j < 8; ++j) {
                    const int c = j * 8 + jlane * 2;
                    float v0 = acc[tt][j][half * 2 + 0];
                    float v1 = acc[tt][j][half * 2 + 1];
                    const float2 r = *(const float2*)(resid + (size_t)row * HCH + c);
                    v0 += r.x; v1 += r.y;
                    *(float2*)(outf + (size_t)row * HCH + c) = make_float2(v0, v1);
                }
            }
        }
    }
}

// ---------------- launch ----------------
extern "C" void kernel_launch(void* const* d_in, const int* in_sizes, int n_in,
                              void* d_out, int out_size)
{
    const float* x   = (const float*)d_in[0];   // [N, 64]
    const float* Wa  = (const float*)d_in[1];   // [27, 64, 64]
    const float* Wb  = (const float*)d_in[2];   // [27, 64, 64]
    const int*   nbr = (const int*)d_in[3];     // [N, 27]
    float* out = (float*)d_out;

    uint2 *pkx = nullptr, *pkm = nullptr;
    __nv_bfloat16* wt = nullptr;
    cudaGetSymbolAddress((void**)&pkx, g_pkx);
    cudaGetSymbolAddress((void**)&pkm, g_pkm);
    cudaGetSymbolAddress((void**)&wt, g_Wt);

    const int totalw = 2 * KOFF * HCH * HCH;
    prep_w<<<(totalw + 255) / 256, 256>>>(Wa, Wb);

    const size_t totalx = (size_t)(N_VOX + 1) * 32;
    prep_x<<<(int)((totalx + 255) / 256), 256>>>(x);

    const int grid = N_VOX / TILE_M;   // 2048
    const size_t wstride = (size_t)KOFF * 2 * WTILE_EL;
    // conv_a + ReLU -> packed mid
    spconv_mma<<<grid, NT>>>(pkx, wt, nbr, nullptr, nullptr, pkm, 1);
    // conv_b + residual -> out
    spconv_mma<<<grid, NT>>>(pkm, wt + wstride, nbr, x, out, nullptr, 0);
}

// round 11
// speedup vs baseline: 1.0879x; 1.0879x over previous
#include <cuda_runtime.h>
#include <cuda_bf16.h>
#include <cstdint>

#define N_VOX 262144
#define HCH   64
#define KOFF  27
#define TILE_M 128
#define NT     128

#define WROW     72                    // padded W^T row: 72 bf16 = 144 B
#define WTILE_EL (HCH * WROW)          // 4608 elems per split tile
#define WTILE_B  (WTILE_EL * 2)        // 9216 B
#define WOFF_B   (2 * WTILE_B)         // 18432 B per offset (hi + lo)

// ---------------- device globals (no allocs allowed) ----------------
// Packed hi/lo bf16 features: pk[row*32 + j] = {bf16x2 hi(2j,2j+1), bf16x2 lo}
// Row N_VOX is the zero sentinel row.
__device__ __align__(16) uint2 g_pkx[(size_t)(N_VOX + 1) * 32];
__device__ __align__(16) uint2 g_pkm[(size_t)(N_VOX + 1) * 32];
__device__ __align__(16) __nv_bfloat16 g_Wt[2][KOFF][2][WTILE_EL];

// ---------------- helpers ----------------
__device__ __forceinline__ uint32_t smem_u32(const void* p) {
    return (uint32_t)__cvta_generic_to_shared(p);
}
__device__ __forceinline__ void cp_async16(uint32_t dst, const void* src) {
    asm volatile("cp.async.ca.shared.global [%0], [%1], 16;" :: "r"(dst), "l"(src));
}
__device__ __forceinline__ void cp_commit() { asm volatile("cp.async.commit_group;"); }
__device__ __forceinline__ void cp_wait0()  { asm volatile("cp.async.wait_group 0;"); }

__device__ __forceinline__ void ldmx4(uint32_t* r, uint32_t addr) {
    asm volatile("ldmatrix.sync.aligned.m8n8.x4.shared.b16 {%0,%1,%2,%3}, [%4];"
                 : "=r"(r[0]), "=r"(r[1]), "=r"(r[2]), "=r"(r[3]) : "r"(addr));
}
__device__ __forceinline__ void mma16816(float* c, const uint32_t* a,
                                         uint32_t b0, uint32_t b1) {
    asm volatile("mma.sync.aligned.m16n8k16.row.col.f32.bf16.bf16.f32 "
                 "{%0,%1,%2,%3}, {%4,%5,%6,%7}, {%8,%9}, {%0,%1,%2,%3};"
                 : "+f"(c[0]), "+f"(c[1]), "+f"(c[2]), "+f"(c[3])
                 : "r"(a[0]), "r"(a[1]), "r"(a[2]), "r"(a[3]), "r"(b0), "r"(b1));
}

// ---------------- W prep: W[k][kin][n] -> W^T[n][kin], hi/lo split, 144B rows
__global__ void prep_w(const float* __restrict__ Wa, const float* __restrict__ Wb) {
    int i = blockIdx.x * blockDim.x + threadIdx.x;
    const int total = KOFF * HCH * HCH;
    if (i >= 2 * total) return;
    const int w = i / total;
    const int r = i - w * total;           // k*4096 + kin*64 + n
    const float v = (w == 0) ? Wa[r] : Wb[r];
    const int k   = r >> 12;
    const int kin = (r >> 6) & 63;
    const int n   = r & 63;
    __nv_bfloat16 hi = __float2bfloat16(v);
    __nv_bfloat16 lo = __float2bfloat16(v - __bfloat162float(hi));
    g_Wt[w][k][0][n * WROW + kin] = hi;
    g_Wt[w][k][1][n * WROW + kin] = lo;
}

// ---------------- x prep: fp32 -> packed hi/lo bf16; also zero sentinel rows
__global__ void prep_x(const float* __restrict__ x) {
    const size_t i = (size_t)blockIdx.x * blockDim.x + threadIdx.x;
    const size_t total = (size_t)(N_VOX + 1) * 32;
    if (i >= total) return;
    uint2 o = make_uint2(0u, 0u);
    if (i < (size_t)N_VOX * 32) {
        const float2 v = ((const float2*)x)[i];
        __nv_bfloat162 h = __floats2bfloat162_rn(v.x, v.y);
        __nv_bfloat162 l = __floats2bfloat162_rn(v.x - __bfloat162float(h.x),
                                                 v.y - __bfloat162float(h.y));
        o.x = *(uint32_t*)&h;
        o.y = *(uint32_t*)&l;
        g_pkx[i] = o;
    } else {
        g_pkx[i] = o;
        g_pkm[i] = o;      // zero sentinel row of mid as well
    }
}

// ---------------- main conv kernel (HMMA mma.sync, packed A, pipelined) -----
__global__ void __launch_bounds__(NT, 3)
spconv_mma(const uint2* __restrict__ pk,               // packed hi/lo feats
           const __nv_bfloat16* __restrict__ wt,       // [KOFF][2][WTILE_EL]
           const int* __restrict__ nbr,
           const float* __restrict__ resid,            // conv_b only
           float* __restrict__ outf,                   // conv_b only
           uint2* __restrict__ outpk)                  // conv_a only (relu+pack)
{
    __shared__ __align__(16) char wbuf[2][WOFF_B];

    const int t    = threadIdx.x;
    const int w    = t >> 5;
    const int lane = t & 31;
    const int row0 = blockIdx.x * TILE_M;
    const int gr   = row0 + 32 * w + (lane >> 2);   // fragment base row

    const uint32_t sb[2] = { smem_u32(wbuf[0]), smem_u32(wbuf[1]) };
    const int q = lane >> 3, e = lane & 7;
    const uint32_t lm_lane = (uint32_t)(((q & 1) * 8 + e) * 144 + (q >> 1) * 16);
    const int jlane = lane & 3;                     // pair-column within fragment

    float acc[2][8][4];
#pragma unroll
    for (int a = 0; a < 2; ++a)
#pragma unroll
        for (int j = 0; j < 8; ++j)
#pragma unroll
            for (int c = 0; c < 4; ++c) acc[a][j][c] = 0.0f;

    int idxc[4], idxn[4];
#define LOAD_IDX(dst, kk) do { \
        dst[0] = __ldg(&nbr[(size_t)(gr)      * KOFF + (kk)]); \
        dst[1] = __ldg(&nbr[(size_t)(gr + 8)  * KOFF + (kk)]); \
        dst[2] = __ldg(&nbr[(size_t)(gr + 16) * KOFF + (kk)]); \
        dst[3] = __ldg(&nbr[(size_t)(gr + 24) * KOFF + (kk)]); } while (0)

    // Load A fragments (both splits) for one 16-wide k-chunk straight from pk.
#define LOAD_APK(Ah, Al, idx, kc) do { \
        const int j0 = (kc) * 8 + jlane; \
        _Pragma("unroll") \
        for (int tt = 0; tt < 2; ++tt) { \
            _Pragma("unroll") \
            for (int h = 0; h < 2; ++h) { \
                const size_t base = (size_t)idx[tt * 2 + h] * 32; \
                const uint2 g0 = __ldg(&pk[base + j0]); \
                const uint2 g1 = __ldg(&pk[base + j0 + 4]); \
                Ah[tt][h]     = g0.x;  Al[tt][h]     = g0.y; \
                Ah[tt][2 + h] = g1.x;  Al[tt][2 + h] = g1.y; \
            } \
        } } while (0)

    // ---- prologue: stage W[0], load idx + A(k=0,kc=0)
    {
        const char* src = (const char*)wt;
        for (int i = t; i < WOFF_B / 16; i += NT)
            cp_async16(sb[0] + i * 16, src + i * 16);
        cp_commit();
    }
    LOAD_IDX(idxc, 0);
    uint32_t cAh[2][4], cAl[2][4];      // current A fragments
    uint32_t nAh[2][4], nAl[2][4];      // prefetched A fragments
    LOAD_APK(cAh, cAl, idxc, 0);
    cp_wait0();
    __syncthreads();

#pragma unroll 1
    for (int k = 0; k < KOFF; ++k) {
        const int b = k & 1;
        if (k < KOFF - 1) {
            const char* src = (const char*)wt + (size_t)(k + 1) * WOFF_B;
            for (int i = t; i < WOFF_B / 16; i += NT)
                cp_async16(sb[b ^ 1] + i * 16, src + i * 16);
            cp_commit();
            LOAD_IDX(idxn, k + 1);
        }
        const uint32_t sbuf = sb[b];

#pragma unroll
        for (int kc = 0; kc < 4; ++kc) {
            // prefetch next A chunk BEFORE consuming current -> latency hidden
            if (kc < 3)              { LOAD_APK(nAh, nAl, idxc, kc + 1); }
            else if (k < KOFF - 1)   { LOAD_APK(nAh, nAl, idxn, 0); }

            // B fragments for this k-chunk
            uint32_t bh[16], bl[16];
#pragma unroll
            for (int u = 0; u < 4; ++u) {
                const uint32_t a0 = sbuf + (uint32_t)(u * 16 * 144 + kc * 32) + lm_lane;
                ldmx4(&bh[u * 4], a0);
                ldmx4(&bl[u * 4], a0 + WTILE_B);
            }

            // 48 MMAs: 2 m-tiles x 8 n-tiles x 3 hi/lo combos
#pragma unroll
            for (int tt = 0; tt < 2; ++tt) {
#pragma unroll
                for (int j = 0; j < 8; ++j) {
                    const int u4 = (j >> 1) * 4 + (j & 1);
                    mma16816(acc[tt][j], cAh[tt], bh[u4], bh[u4 + 2]);
                    mma16816(acc[tt][j], cAh[tt], bl[u4], bl[u4 + 2]);
                    mma16816(acc[tt][j], cAl[tt], bh[u4], bh[u4 + 2]);
                }
            }

            // rotate prefetched fragments into current
#pragma unroll
            for (int tt = 0; tt < 2; ++tt)
#pragma unroll
                for (int i = 0; i < 4; ++i) {
                    cAh[tt][i] = nAh[tt][i];
                    cAl[tt][i] = nAl[tt][i];
                }
        }

        if (k < KOFF - 1) cp_wait0();
        __syncthreads();
        idxc[0] = idxn[0]; idxc[1] = idxn[1];
        idxc[2] = idxn[2]; idxc[3] = idxn[3];
    }

    // ---- epilogue ----
    if (outpk) {
        // conv_a: relu, split to hi/lo, packed store (feeds conv_b's gather)
#pragma unroll
        for (int tt = 0; tt < 2; ++tt) {
#pragma unroll
            for (int half = 0; half < 2; ++half) {
                const int row = gr + 16 * tt + 8 * half;
#pragma unroll
                for (int j = 0; j < 8; ++j) {
                    float v0 = fmaxf(acc[tt][j][half * 2 + 0], 0.f);
                    float v1 = fmaxf(acc[tt][j][half * 2 + 1], 0.f);
                    __nv_bfloat162 h = __floats2bfloat162_rn(v0, v1);
                    __nv_bfloat162 l = __floats2bfloat162_rn(v0 - __bfloat162float(h.x),
                                                             v1 - __bfloat162float(h.y));
                    outpk[(size_t)row * 32 + j * 4 + jlane] =
                        make_uint2(*(uint32_t*)&h, *(uint32_t*)&l);
                }
            }
        }
    } else {
        // conv_b: residual add, fp32 store
#pragma unroll
        for (int tt = 0; tt < 2; ++tt) {
#pragma unroll
            for (int half = 0; half < 2; ++half) {
                const int row = gr + 16 * tt + 8 * half;
#pragma unroll
                for (int j = 0; j < 8; ++j) {
                    const int c = j * 8 + jlane * 2;
                    float v0 = acc[tt][j][half * 2 + 0];
                    float v1 = acc[tt][j][half * 2 + 1];
                    const float2 r = *(const float2*)(resid + (size_t)row * HCH + c);
                    v0 += r.x; v1 += r.y;
                    *(float2*)(outf + (size_t)row * HCH + c) = make_float2(v0, v1);
                }
            }
        }
    }
}

// ---------------- launch ----------------
extern "C" void kernel_launch(void* const* d_in, const int* in_sizes, int n_in,
                              void* d_out, int out_size)
{
    const float* x   = (const float*)d_in[0];   // [N, 64]
    const float* Wa  = (const float*)d_in[1];   // [27, 64, 64]
    const float* Wb  = (const float*)d_in[2];   // [27, 64, 64]
    const int*   nbr = (const int*)d_in[3];     // [N, 27]
    float* out = (float*)d_out;

    uint2 *pkx = nullptr, *pkm = nullptr;
    __nv_bfloat16* wt = nullptr;
    cudaGetSymbolAddress((void**)&pkx, g_pkx);
    cudaGetSymbolAddress((void**)&pkm, g_pkm);
    cudaGetSymbolAddress((void**)&wt, g_Wt);

    const int totalw = 2 * KOFF * HCH * HCH;
    prep_w<<<(totalw + 255) / 256, 256>>>(Wa, Wb);

    const size_t totalx = (size_t)(N_VOX + 1) * 32;
    prep_x<<<(int)((totalx + 255) / 256), 256>>>(x);

    const int grid = N_VOX / TILE_M;   // 2048
    const size_t wstride = (size_t)KOFF * 2 * WTILE_EL;
    // conv_a + ReLU -> packed mid
    spconv_mma<<<grid, NT>>>(pkx, wt, nbr, nullptr, nullptr, pkm);
    // conv_b + residual -> out
    spconv_mma<<<grid, NT>>>(pkm, wt + wstride, nbr, x, out, nullptr);
}

// round 12
// speedup vs baseline: 1.0886x; 1.0007x over previous
#include <cuda_runtime.h>
#include <cuda_bf16.h>
#include <cstdint>

#define N_VOX 262144
#define HCH   64
#define KOFF  27
#define TILE_M 128
#define NT     128

#define WROW     72                    // padded W^T row: 72 bf16 = 144 B
#define WTILE_EL (HCH * WROW)          // 4608 elems per split tile
#define WTILE_B  (WTILE_EL * 2)        // 9216 B
#define WOFF_B   (2 * WTILE_B)         // 18432 B per offset (hi + lo)

// ---------------- device globals (no allocs allowed) ----------------
// Packed hi/lo bf16 features: pk[row*32 + j] = {bf16x2 hi(2j,2j+1), bf16x2 lo}
// Row N_VOX is the zero sentinel row.
__device__ __align__(16) uint2 g_pkx[(size_t)(N_VOX + 1) * 32];
__device__ __align__(16) uint2 g_pkm[(size_t)(N_VOX + 1) * 32];
__device__ __align__(16) __nv_bfloat16 g_Wt[2][KOFF][2][WTILE_EL];

// ---------------- helpers ----------------
__device__ __forceinline__ uint32_t smem_u32(const void* p) {
    return (uint32_t)__cvta_generic_to_shared(p);
}
__device__ __forceinline__ void cp_async16(uint32_t dst, const void* src) {
    asm volatile("cp.async.ca.shared.global [%0], [%1], 16;" :: "r"(dst), "l"(src));
}
__device__ __forceinline__ void cp_commit() { asm volatile("cp.async.commit_group;"); }
__device__ __forceinline__ void cp_wait0()  { asm volatile("cp.async.wait_group 0;"); }

__device__ __forceinline__ void ldmx4(uint32_t* r, uint32_t addr) {
    asm volatile("ldmatrix.sync.aligned.m8n8.x4.shared.b16 {%0,%1,%2,%3}, [%4];"
                 : "=r"(r[0]), "=r"(r[1]), "=r"(r[2]), "=r"(r[3]) : "r"(addr));
}
__device__ __forceinline__ void mma16816(float* c, const uint32_t* a,
                                         uint32_t b0, uint32_t b1) {
    asm volatile("mma.sync.aligned.m16n8k16.row.col.f32.bf16.bf16.f32 "
                 "{%0,%1,%2,%3}, {%4,%5,%6,%7}, {%8,%9}, {%0,%1,%2,%3};"
                 : "+f"(c[0]), "+f"(c[1]), "+f"(c[2]), "+f"(c[3])
                 : "r"(a[0]), "r"(a[1]), "r"(a[2]), "r"(a[3]), "r"(b0), "r"(b1));
}

// ---------------- W prep: W[k][kin][n] -> W^T[n][kin], hi/lo split, 144B rows
__global__ void prep_w(const float* __restrict__ Wa, const float* __restrict__ Wb) {
    int i = blockIdx.x * blockDim.x + threadIdx.x;
    const int total = KOFF * HCH * HCH;
    if (i >= 2 * total) return;
    const int w = i / total;
    const int r = i - w * total;           // k*4096 + kin*64 + n
    const float v = (w == 0) ? Wa[r] : Wb[r];
    const int k   = r >> 12;
    const int kin = (r >> 6) & 63;
    const int n   = r & 63;
    __nv_bfloat16 hi = __float2bfloat16(v);
    __nv_bfloat16 lo = __float2bfloat16(v - __bfloat162float(hi));
    g_Wt[w][k][0][n * WROW + kin] = hi;
    g_Wt[w][k][1][n * WROW + kin] = lo;
}

// ---------------- x prep: fp32 -> packed hi/lo bf16; also zero sentinel rows
__global__ void prep_x(const float* __restrict__ x) {
    const size_t i = (size_t)blockIdx.x * blockDim.x + threadIdx.x;
    const size_t total = (size_t)(N_VOX + 1) * 32;
    if (i >= total) return;
    uint2 o = make_uint2(0u, 0u);
    if (i < (size_t)N_VOX * 32) {
        const float2 v = ((const float2*)x)[i];
        __nv_bfloat162 h = __floats2bfloat162_rn(v.x, v.y);
        __nv_bfloat162 l = __floats2bfloat162_rn(v.x - __bfloat162float(h.x),
                                                 v.y - __bfloat162float(h.y));
        o.x = *(uint32_t*)&h;
        o.y = *(uint32_t*)&l;
        g_pkx[i] = o;
    } else {
        g_pkx[i] = o;
        g_pkm[i] = o;      // zero sentinel row of mid as well
    }
}

// ---------------- main conv kernel (HMMA mma.sync, packed A, pipelined) -----
__global__ void __launch_bounds__(NT, 3)
spconv_mma(const uint2* __restrict__ pk,               // packed hi/lo feats
           const __nv_bfloat16* __restrict__ wt,       // [KOFF][2][WTILE_EL]
           const int* __restrict__ nbr,
           const float* __restrict__ resid,            // conv_b only
           float* __restrict__ outf,                   // conv_b only
           uint2* __restrict__ outpk)                  // conv_a only (relu+pack)
{
    __shared__ __align__(16) char wbuf[2][WOFF_B];

    const int t    = threadIdx.x;
    const int w    = t >> 5;
    const int lane = t & 31;
    const int row0 = blockIdx.x * TILE_M;
    const int gr   = row0 + 32 * w + (lane >> 2);   // fragment base row

    const uint32_t sb[2] = { smem_u32(wbuf[0]), smem_u32(wbuf[1]) };
    const int q = lane >> 3, e = lane & 7;
    const uint32_t lm_lane = (uint32_t)(((q & 1) * 8 + e) * 144 + (q >> 1) * 16);
    const int jlane = lane & 3;                     // pair-column within fragment

    float acc[2][8][4];
#pragma unroll
    for (int a = 0; a < 2; ++a)
#pragma unroll
        for (int j = 0; j < 8; ++j)
#pragma unroll
            for (int c = 0; c < 4; ++c) acc[a][j][c] = 0.0f;

    int idxc[4], idxn[4];
#define LOAD_IDX(dst, kk) do { \
        dst[0] = __ldg(&nbr[(size_t)(gr)      * KOFF + (kk)]); \
        dst[1] = __ldg(&nbr[(size_t)(gr + 8)  * KOFF + (kk)]); \
        dst[2] = __ldg(&nbr[(size_t)(gr + 16) * KOFF + (kk)]); \
        dst[3] = __ldg(&nbr[(size_t)(gr + 24) * KOFF + (kk)]); } while (0)

    // Load A fragments (both splits) for one 16-wide k-chunk straight from pk.
#define LOAD_APK(Ah, Al, idx, kc) do { \
        const int j0 = (kc) * 8 + jlane; \
        _Pragma("unroll") \
        for (int tt = 0; tt < 2; ++tt) { \
            _Pragma("unroll") \
            for (int h = 0; h < 2; ++h) { \
                const size_t base = (size_t)idx[tt * 2 + h] * 32; \
                const uint2 g0 = __ldg(&pk[base + j0]); \
                const uint2 g1 = __ldg(&pk[base + j0 + 4]); \
                Ah[tt][h]     = g0.x;  Al[tt][h]     = g0.y; \
                Ah[tt][2 + h] = g1.x;  Al[tt][2 + h] = g1.y; \
            } \
        } } while (0)

    // ---- prologue: stage W[0], load idx + A(k=0,kc=0)
    {
        const char* src = (const char*)wt;
        for (int i = t; i < WOFF_B / 16; i += NT)
            cp_async16(sb[0] + i * 16, src + i * 16);
        cp_commit();
    }
    LOAD_IDX(idxc, 0);
    uint32_t cAh[2][4], cAl[2][4];      // current A fragments
    uint32_t nAh[2][4], nAl[2][4];      // prefetched A fragments
    LOAD_APK(cAh, cAl, idxc, 0);
    cp_wait0();
    __syncthreads();

#pragma unroll 1
    for (int k = 0; k < KOFF; ++k) {
        const int b = k & 1;
        if (k < KOFF - 1) {
            const char* src = (const char*)wt + (size_t)(k + 1) * WOFF_B;
            for (int i = t; i < WOFF_B / 16; i += NT)
                cp_async16(sb[b ^ 1] + i * 16, src + i * 16);
            cp_commit();
            LOAD_IDX(idxn, k + 1);
        }
        const uint32_t sbuf = sb[b];

#pragma unroll
        for (int kc = 0; kc < 4; ++kc) {
            // prefetch next A chunk BEFORE consuming current -> latency hidden
            if (kc < 3)              { LOAD_APK(nAh, nAl, idxc, kc + 1); }
            else if (k < KOFF - 1)   { LOAD_APK(nAh, nAl, idxn, 0); }

            // B fragments for this k-chunk
            uint32_t bh[16], bl[16];
#pragma unroll
            for (int u = 0; u < 4; ++u) {
                const uint32_t a0 = sbuf + (uint32_t)(u * 16 * 144 + kc * 32) + lm_lane;
                ldmx4(&bh[u * 4], a0);
                ldmx4(&bl[u * 4], a0 + WTILE_B);
            }

            // 48 MMAs: 2 m-tiles x 8 n-tiles x 3 hi/lo combos
#pragma unroll
            for (int tt = 0; tt < 2; ++tt) {
#pragma unroll
                for (int j = 0; j < 8; ++j) {
                    const int u4 = (j >> 1) * 4 + (j & 1);
                    mma16816(acc[tt][j], cAh[tt], bh[u4], bh[u4 + 2]);
                    mma16816(acc[tt][j], cAh[tt], bl[u4], bl[u4 + 2]);
                    mma16816(acc[tt][j], cAl[tt], bh[u4], bh[u4 + 2]);
                }
            }

            // rotate prefetched fragments into current
#pragma unroll
            for (int tt = 0; tt < 2; ++tt)
#pragma unroll
                for (int i = 0; i < 4; ++i) {
                    cAh[tt][i] = nAh[tt][i];
                    cAl[tt][i] = nAl[tt][i];
                }
        }

        if (k < KOFF - 1) cp_wait0();
        __syncthreads();
        idxc[0] = idxn[0]; idxc[1] = idxn[1];
        idxc[2] = idxn[2]; idxc[3] = idxn[3];
    }

    // ---- epilogue ----
    if (outpk) {
        // conv_a: relu, split to hi/lo, packed store (feeds conv_b's gather)
#pragma unroll
        for (int tt = 0; tt < 2; ++tt) {
#pragma unroll
            for (int half = 0; half < 2; ++half) {
                const int row = gr + 16 * tt + 8 * half;
#pragma unroll
                for (int j = 0; j < 8; ++j) {
                    float v0 = fmaxf(acc[tt][j][half * 2 + 0], 0.f);
                    float v1 = fmaxf(acc[tt][j][half * 2 + 1], 0.f);
                    __nv_bfloat162 h = __floats2bfloat162_rn(v0, v1);
                    __nv_bfloat162 l = __floats2bfloat162_rn(v0 - __bfloat162float(h.x),
                                                             v1 - __bfloat162float(h.y));
                    outpk[(size_t)row * 32 + j * 4 + jlane] =
                        make_uint2(*(uint32_t*)&h, *(uint32_t*)&l);
                }
            }
        }
    } else {
        // conv_b: residual add, fp32 store
#pragma unroll
        for (int tt = 0; tt < 2; ++tt) {
#pragma unroll
            for (int half = 0; half < 2; ++half) {
                const int row = gr + 16 * tt + 8 * half;
#pragma unroll
                for (int j = 0; j < 8; ++j) {
                    const int c = j * 8 + jlane * 2;
                    float v0 = acc[tt][j][half * 2 + 0];
                    float v1 = acc[tt][j][half * 2 + 1];
                    const float2 r = *(const float2*)(resid + (size_t)row * HCH + c);
                    v0 += r.x; v1 += r.y;
                    *(float2*)(outf + (size_t)row * HCH + c) = make_float2(v0, v1);
                }
            }
        }
    }
}

// ---------------- launch ----------------
extern "C" void kernel_launch(void* const* d_in, const int* in_sizes, int n_in,
                              void* d_out, int out_size)
{
    const float* x   = (const float*)d_in[0];   // [N, 64]
    const float* Wa  = (const float*)d_in[1];   // [27, 64, 64]
    const float* Wb  = (const float*)d_in[2];   // [27, 64, 64]
    const int*   nbr = (const int*)d_in[3];     // [N, 27]
    float* out = (float*)d_out;

    uint2 *pkx = nullptr, *pkm = nullptr;
    __nv_bfloat16* wt = nullptr;
    cudaGetSymbolAddress((void**)&pkx, g_pkx);
    cudaGetSymbolAddress((void**)&pkm, g_pkm);
    cudaGetSymbolAddress((void**)&wt, g_Wt);

    const int totalw = 2 * KOFF * HCH * HCH;
    prep_w<<<(totalw + 255) / 256, 256>>>(Wa, Wb);

    const size_t totalx = (size_t)(N_VOX + 1) * 32;
    prep_x<<<(int)((totalx + 255) / 256), 256>>>(x);

    const int grid = N_VOX / TILE_M;   // 2048
    const size_t wstride = (size_t)KOFF * 2 * WTILE_EL;
    // conv_a + ReLU -> packed mid
    spconv_mma<<<grid, NT>>>(pkx, wt, nbr, nullptr, nullptr, pkm);
    // conv_b + residual -> out
    spconv_mma<<<grid, NT>>>(pkm, wt + wstride, nbr, x, out, nullptr);
}